// round 1
// baseline (speedup 1.0000x reference)
#include <cuda_runtime.h>
#include <cstdint>

#define BS 256
#define D  2048
#define H  1024
#define C  200
#define NC 112

// ---------------- scratch (static device allocations only) ----------------
__device__ float g_y1[C * H];        // 1 + l2norm(y_embedding)
__device__ float g_c1[2 * NC * H];   // 1 + l2norm(c_embedding)
__device__ float g_hxy[BS * H];      // dropout(x @ xy_fc1^T + b)
__device__ float g_hxc[BS * H];      // dropout(x @ xc_fc1^T + b)
__device__ float g_pn[NC * H];       // sum_h ce_neg[n,h] * W[j, n*H+h]
__device__ float g_pd[NC * H];       // sum_h (ce_pos-ce_neg)[n,h] * W[j, n*H+h]
__device__ float g_base[H];          // bias[j] + sum_n pn[n,j]
__device__ float g_cproj[BS * H];

// ---------------- JAX threefry2x32 (partitionable semantics) --------------
__device__ __forceinline__ uint32_t rotl32(uint32_t v, int r) {
    return (v << r) | (v >> (32 - r));
}

__device__ __forceinline__ void tf2x32(uint32_t k0, uint32_t k1,
                                       uint32_t x0, uint32_t x1,
                                       uint32_t& o0, uint32_t& o1) {
    uint32_t ks2 = k0 ^ k1 ^ 0x1BD11BDAu;
    x0 += k0; x1 += k1;
#define TF_R(r) { x0 += x1; x1 = rotl32(x1, r); x1 ^= x0; }
    TF_R(13) TF_R(15) TF_R(26) TF_R(6)   x0 += k1;  x1 += ks2 + 1u;
    TF_R(17) TF_R(29) TF_R(16) TF_R(24)  x0 += ks2; x1 += k0 + 2u;
    TF_R(13) TF_R(15) TF_R(26) TF_R(6)   x0 += k0;  x1 += k1 + 3u;
    TF_R(17) TF_R(29) TF_R(16) TF_R(24)  x0 += k1;  x1 += ks2 + 4u;
    TF_R(13) TF_R(15) TF_R(26) TF_R(6)   x0 += ks2; x1 += k0 + 5u;
#undef TF_R
    o0 = x0; o1 = x1;
}

// keep-mask for flat element idx under derived key (ka,kb):
// bits = xor of the two threefry words with counter (0, idx)  [partitionable]
// u = bitcast((bits>>9)|0x3f800000) - 1 ;  keep = u < 0.8f
__device__ __forceinline__ bool drop_keep(uint32_t ka, uint32_t kb, uint32_t idx) {
    uint32_t a, b;
    tf2x32(ka, kb, 0u, idx, a, b);
    uint32_t bits = a ^ b;
    float u = __uint_as_float((bits >> 9) | 0x3F800000u) - 1.0f;
    return u < 0.8f;
}

// ---------------- kernel 1: 1 + l2norm rows -------------------------------
__global__ __launch_bounds__(256) void norm_kernel(const float* __restrict__ ye,
                                                   const float* __restrict__ ce) {
    __shared__ float red[256];
    int r = blockIdx.x;
    const float* src;
    float* dst;
    if (r < C) { src = ye + (size_t)r * H;        dst = g_y1 + (size_t)r * H; }
    else       { src = ce + (size_t)(r - C) * H;  dst = g_c1 + (size_t)(r - C) * H; }
    int t = threadIdx.x;
    float4 v = *reinterpret_cast<const float4*>(&src[t * 4]);
    red[t] = v.x * v.x + v.y * v.y + v.z * v.z + v.w * v.w;
    __syncthreads();
    for (int o = 128; o; o >>= 1) {
        if (t < o) red[t] += red[t + o];
        __syncthreads();
    }
    float n = fmaxf(sqrtf(red[0]), 1e-12f);
    dst[t * 4 + 0] = 1.0f + v.x / n;
    dst[t * 4 + 1] = 1.0f + v.y / n;
    dst[t * 4 + 2] = 1.0f + v.z / n;
    dst[t * 4 + 3] = 1.0f + v.w / n;
}

// ---------------- kernel 2: fc1 GEMMs + bias + dropout --------------------
// h = dropout(x(256x2048) @ W(1024x2048)^T + b) ; z selects xy / xc
__global__ __launch_bounds__(256) void fc1_kernel(const float* __restrict__ x,
                                                  const float* __restrict__ w0,
                                                  const float* __restrict__ b0,
                                                  const float* __restrict__ w1,
                                                  const float* __restrict__ b1) {
    __shared__ float As[32][64];  // [k][m]
    __shared__ float Bs[32][64];  // [k][n]
    const int which = blockIdx.z;
    const float* W = which ? w1 : w0;
    const float* B = which ? b1 : b0;
    float* out = which ? g_hxc : g_hxy;
    const int n0 = blockIdx.x * 64;
    const int m0 = blockIdx.y * 64;
    const int tid = threadIdx.x;
    const int tx = tid % 16, ty = tid / 16;
    const int lr = tid / 8;          // 0..31
    const int lc = (tid % 8) * 4;    // 0..28
    float acc[4][4] = {};
    for (int k0 = 0; k0 < D; k0 += 32) {
#pragma unroll
        for (int rr = 0; rr < 2; rr++) {
            int r = lr + rr * 32;
            float4 va = *reinterpret_cast<const float4*>(&x[(size_t)(m0 + r) * D + k0 + lc]);
            As[lc + 0][r] = va.x; As[lc + 1][r] = va.y;
            As[lc + 2][r] = va.z; As[lc + 3][r] = va.w;
            float4 vb = *reinterpret_cast<const float4*>(&W[(size_t)(n0 + r) * D + k0 + lc]);
            Bs[lc + 0][r] = vb.x; Bs[lc + 1][r] = vb.y;
            Bs[lc + 2][r] = vb.z; Bs[lc + 3][r] = vb.w;
        }
        __syncthreads();
#pragma unroll
        for (int kk = 0; kk < 32; kk++) {
            float4 a = *reinterpret_cast<const float4*>(&As[kk][ty * 4]);
            float4 b = *reinterpret_cast<const float4*>(&Bs[kk][tx * 4]);
            float av[4] = {a.x, a.y, a.z, a.w};
            float bv[4] = {b.x, b.y, b.z, b.w};
#pragma unroll
            for (int i = 0; i < 4; i++)
#pragma unroll
                for (int j = 0; j < 4; j++)
                    acc[i][j] = fmaf(av[i], bv[j], acc[i][j]);
        }
        __syncthreads();
    }
    uint32_t ka, kb;
    tf2x32(0u, 42u, 0u, (uint32_t)which, ka, kb);  // k1/k2 via fold_in(key42, which)
#pragma unroll
    for (int i = 0; i < 4; i++) {
        int b = m0 + ty * 4 + i;
#pragma unroll
        for (int j = 0; j < 4; j++) {
            int col = n0 + tx * 4 + j;
            float h = acc[i][j] + B[col];
            uint32_t idx = (uint32_t)(b * H + col);
            out[(size_t)b * H + col] = drop_keep(ka, kb, idx) ? h / 0.8f : 0.0f;
        }
    }
}

// ---------------- kernel 3: stream concept_proj_w once --------------------
// pn[n,j] = <ce_neg[n,:], W[j, n*H:...]> ; pd[n,j] = <ce_pos-ce_neg, ...>
__global__ __launch_bounds__(256) void pnd_kernel(const float* __restrict__ ce,
                                                  const float* __restrict__ W) {
    __shared__ float s_en[H];
    __shared__ float s_ed[H];
    const int n = blockIdx.x;          // 0..111
    const int jg = blockIdx.y;         // 0..127 (groups of 8 j)
    const int tid = threadIdx.x;
    {
        int i = tid * 4;
        float4 ep = *reinterpret_cast<const float4*>(&ce[(size_t)n * H + i]);
        float4 en = *reinterpret_cast<const float4*>(&ce[(size_t)(NC + n) * H + i]);
        *reinterpret_cast<float4*>(&s_en[i]) = en;
        float4 ed = make_float4(ep.x - en.x, ep.y - en.y, ep.z - en.z, ep.w - en.w);
        *reinterpret_cast<float4*>(&s_ed[i]) = ed;
    }
    __syncthreads();
    const int w = tid / 32, lane = tid % 32;
    const int j = jg * 8 + w;
    const float* Wr = W + (size_t)j * (NC * H) + (size_t)n * H;
    float pn = 0.f, pd = 0.f;
#pragma unroll
    for (int c = 0; c < 8; c++) {
        int hh = c * 128 + lane * 4;
        float4 wv = *reinterpret_cast<const float4*>(&Wr[hh]);
        float4 en = *reinterpret_cast<const float4*>(&s_en[hh]);
        float4 ed = *reinterpret_cast<const float4*>(&s_ed[hh]);
        pn += wv.x * en.x + wv.y * en.y + wv.z * en.z + wv.w * en.w;
        pd += wv.x * ed.x + wv.y * ed.y + wv.z * ed.z + wv.w * ed.w;
    }
#pragma unroll
    for (int off = 16; off; off >>= 1) {
        pn += __shfl_down_sync(0xFFFFFFFFu, pn, off);
        pd += __shfl_down_sync(0xFFFFFFFFu, pd, off);
    }
    if (lane == 0) {
        g_pn[n * H + j] = pn;
        g_pd[n * H + j] = pd;
    }
}

// ---------------- kernel 4: base[j] = bias[j] + sum_n pn[n,j] -------------
__global__ __launch_bounds__(256) void base_kernel(const float* __restrict__ bias) {
    int j = blockIdx.x * 256 + threadIdx.x;
    float a = bias[j];
    for (int n = 0; n < NC; n++) a += g_pn[n * H + j];
    g_base[j] = a;
}

// ---------------- kernel 5: c_proj = base + gt @ pd -----------------------
__global__ __launch_bounds__(256) void cproj_kernel(const int* __restrict__ cgt) {
    __shared__ float As[16][64];  // [k=n][b]
    __shared__ float Bs[16][64];  // [k=n][j]
    const int n0 = blockIdx.x * 64;
    const int m0 = blockIdx.y * 64;
    const int tid = threadIdx.x;
    const int tx = tid % 16, ty = tid / 16;
    float acc[4][4] = {};
    for (int k0 = 0; k0 < NC; k0 += 16) {
        {
            int r = tid / 4;
            int c = (tid % 4) * 4;
            int b = m0 + r;
#pragma unroll
            for (int q = 0; q < 4; q++)
                As[c + q][r] = (cgt[(size_t)b * NC + k0 + c + q] == 1) ? 1.0f : 0.0f;
        }
        {
            int kk = tid / 16;
            int j4 = (tid % 16) * 4;
            float4 v = *reinterpret_cast<const float4*>(&g_pd[(size_t)(k0 + kk) * H + n0 + j4]);
            *reinterpret_cast<float4*>(&Bs[kk][j4]) = v;
        }
        __syncthreads();
#pragma unroll
        for (int kk = 0; kk < 16; kk++) {
            float4 a = *reinterpret_cast<const float4*>(&As[kk][ty * 4]);
            float4 b = *reinterpret_cast<const float4*>(&Bs[kk][tx * 4]);
            float av[4] = {a.x, a.y, a.z, a.w};
            float bv[4] = {b.x, b.y, b.z, b.w};
#pragma unroll
            for (int i = 0; i < 4; i++)
#pragma unroll
                for (int j = 0; j < 4; j++)
                    acc[i][j] = fmaf(av[i], bv[j], acc[i][j]);
        }
        __syncthreads();
    }
#pragma unroll
    for (int i = 0; i < 4; i++) {
        int b = m0 + ty * 4 + i;
#pragma unroll
        for (int j = 0; j < 4; j++) {
            int col = n0 + tx * 4 + j;
            g_cproj[(size_t)b * H + col] = acc[i][j] + g_base[col];
        }
    }
}

// ---------------- kernel 6: xy_energy + cy_energy -------------------------
// out[b,c] = sum_h relu(A[b,h]*(1+ynorm[c,h])) * clsw[h] + clsb
__global__ __launch_bounds__(256) void xycy_kernel(const float* __restrict__ clsw_xy,
                                                   const float* __restrict__ clsb_xy,
                                                   const float* __restrict__ clsw_cy,
                                                   const float* __restrict__ clsb_cy,
                                                   float* __restrict__ out) {
    __shared__ float Hs[32][33];  // [k][b]
    __shared__ float Ys[32][33];  // [k][c]
    __shared__ float ws[32];
    const int z = blockIdx.z;
    const float* A = z ? g_cproj : g_hxy;
    const float* clsw = z ? clsw_cy : clsw_xy;
    const float bias = z ? clsb_cy[0] : clsb_xy[0];
    const int c0 = blockIdx.x * 32;
    const int b0 = blockIdx.y * 32;
    const int tid = threadIdx.x;
    const int tx = tid % 16, ty = tid / 16;
    const int lr = tid / 8;
    const int lc = (tid % 8) * 4;
    float acc[2][2] = {};
    for (int k0 = 0; k0 < H; k0 += 32) {
        {
            float4 v = *reinterpret_cast<const float4*>(&A[(size_t)(b0 + lr) * H + k0 + lc]);
            Hs[lc + 0][lr] = v.x; Hs[lc + 1][lr] = v.y;
            Hs[lc + 2][lr] = v.z; Hs[lc + 3][lr] = v.w;
            int cr = c0 + lr; if (cr > C - 1) cr = C - 1;
            float4 u = *reinterpret_cast<const float4*>(&g_y1[(size_t)cr * H + k0 + lc]);
            Ys[lc + 0][lr] = u.x; Ys[lc + 1][lr] = u.y;
            Ys[lc + 2][lr] = u.z; Ys[lc + 3][lr] = u.w;
            if (tid < 32) ws[tid] = clsw[k0 + tid];
        }
        __syncthreads();
#pragma unroll
        for (int kk = 0; kk < 32; kk++) {
            float a0 = Hs[kk][ty * 2 + 0];
            float a1 = Hs[kk][ty * 2 + 1];
            float y0 = Ys[kk][tx * 2 + 0];
            float y1v = Ys[kk][tx * 2 + 1];
            float w = ws[kk];
            acc[0][0] = fmaf(fmaxf(a0 * y0, 0.f), w, acc[0][0]);
            acc[0][1] = fmaf(fmaxf(a0 * y1v, 0.f), w, acc[0][1]);
            acc[1][0] = fmaf(fmaxf(a1 * y0, 0.f), w, acc[1][0]);
            acc[1][1] = fmaf(fmaxf(a1 * y1v, 0.f), w, acc[1][1]);
        }
        __syncthreads();
    }
    const size_t obase = z ? (size_t)(BS * C) : 0;
#pragma unroll
    for (int i = 0; i < 2; i++) {
        int b = b0 + ty * 2 + i;
#pragma unroll
        for (int j = 0; j < 2; j++) {
            int c = c0 + tx * 2 + j;
            if (c < C) out[obase + (size_t)b * C + c] = acc[i][j] + bias;
        }
    }
}

// ---------------- kernel 7: xc_energy -------------------------------------
// out[b,n,s] = sum_h relu(hxc[b,h]*(1+cnorm[s*N+n,h])) * xc_w[n,h] + xc_b[n]
__global__ __launch_bounds__(256) void xc_kernel(const float* __restrict__ xcw,
                                                 const float* __restrict__ xcb,
                                                 float* __restrict__ out) {
    __shared__ float Hs[32][33];  // [k][b]
    __shared__ float Cs[32][17];  // [k][n_local*2+s]
    __shared__ float Ws[32][9];   // [k][n_local]
    const int n0 = blockIdx.x * 8;
    const int b0 = blockIdx.y * 32;
    const int tid = threadIdx.x;
    const int tx = tid % 8;   // n_local
    const int ty = tid / 8;   // b_local 0..31
    const int lr = tid / 8;
    const int lc = (tid % 8) * 4;
    float acc0 = 0.f, acc1 = 0.f;
    for (int k0 = 0; k0 < H; k0 += 32) {
        {
            float4 v = *reinterpret_cast<const float4*>(&g_hxc[(size_t)(b0 + lr) * H + k0 + lc]);
            Hs[lc + 0][lr] = v.x; Hs[lc + 1][lr] = v.y;
            Hs[lc + 2][lr] = v.z; Hs[lc + 3][lr] = v.w;
        }
        {
            int loc = tid / 16;           // 0..15 => n_local = loc/2, s = loc%2
            int kk = (tid % 16) * 2;
            int nl = loc >> 1, s = loc & 1;
            int row = s * NC + (n0 + nl);
            float2 v = *reinterpret_cast<const float2*>(&g_c1[(size_t)row * H + k0 + kk]);
            Cs[kk + 0][nl * 2 + s] = v.x;
            Cs[kk + 1][nl * 2 + s] = v.y;
        }
        {
            int nl = tid / 32;            // 0..7
            int kk = tid % 32;
            Ws[kk][nl] = xcw[(size_t)(n0 + nl) * H + k0 + kk];
        }
        __syncthreads();
#pragma unroll
        for (int kk = 0; kk < 32; kk++) {
            float h = Hs[kk][ty];
            float w = Ws[kk][tx];
            float cp = Cs[kk][tx * 2 + 0];
            float cn = Cs[kk][tx * 2 + 1];
            acc0 = fmaf(fmaxf(h * cp, 0.f), w, acc0);
            acc1 = fmaf(fmaxf(h * cn, 0.f), w, acc1);
        }
        __syncthreads();
    }
    int b = b0 + ty, n = n0 + tx;
    float bb = xcb[n];
    size_t base = (size_t)(2 * BS * C) + (size_t)b * (NC * 2) + n * 2;
    out[base + 0] = acc0 + bb;
    out[base + 1] = acc1 + bb;
}

// ---------------- launch ---------------------------------------------------
extern "C" void kernel_launch(void* const* d_in, const int* in_sizes, int n_in,
                              void* d_out, int out_size) {
    (void)in_sizes; (void)n_in; (void)out_size;
    const float* x       = (const float*)d_in[0];
    const int*   c_gt    = (const int*)d_in[1];
    const float* y_emb   = (const float*)d_in[2];
    const float* c_emb   = (const float*)d_in[3];
    const float* xy_w    = (const float*)d_in[4];
    const float* xy_b    = (const float*)d_in[5];
    const float* xc_w1   = (const float*)d_in[6];
    const float* xc_b1   = (const float*)d_in[7];
    const float* clsxy_w = (const float*)d_in[8];
    const float* clsxy_b = (const float*)d_in[9];
    const float* clscy_w = (const float*)d_in[10];
    const float* clscy_b = (const float*)d_in[11];
    const float* xcw     = (const float*)d_in[12];
    const float* xcb     = (const float*)d_in[13];
    const float* cpw     = (const float*)d_in[14];
    const float* cpb     = (const float*)d_in[15];
    float* out = (float*)d_out;

    norm_kernel<<<C + 2 * NC, 256>>>(y_emb, c_emb);
    fc1_kernel<<<dim3(H / 64, BS / 64, 2), 256>>>(x, xy_w, xy_b, xc_w1, xc_b1);
    pnd_kernel<<<dim3(NC, H / 8), 256>>>(c_emb, cpw);
    base_kernel<<<H / 256, 256>>>(cpb);
    cproj_kernel<<<dim3(H / 64, BS / 64), 256>>>(c_gt);
    xycy_kernel<<<dim3((C + 31) / 32, BS / 32, 2), 256>>>(clsxy_w, clsxy_b, clscy_w, clscy_b, out);
    xc_kernel<<<dim3(NC / 8, BS / 32), 256>>>(xcw, xcb, out);
}

// round 3
// speedup vs baseline: 1.0800x; 1.0800x over previous
#include <cuda_runtime.h>
#include <cstdint>

#define BS 256
#define D  2048
#define H  1024
#define C  200
#define NC 112

// ---------------- scratch (static device allocations only) ----------------
__device__ float g_y1[C * H];        // 1 + l2norm(y_embedding)
__device__ float g_c1[2 * NC * H];   // 1 + l2norm(c_embedding)
__device__ float g_hxy[BS * H];      // dropout(x @ xy_fc1^T + b)
__device__ float g_hxc[BS * H];      // dropout(x @ xc_fc1^T + b)
__device__ float g_pn[NC * H];       // sum_h ce_neg[n,h] * W[j, n*H+h]
__device__ float g_pd[NC * H];       // sum_h (ce_pos-ce_neg)[n,h] * W[j, n*H+h]
__device__ float g_cproj[BS * H];

// ---------------- JAX threefry2x32 (partitionable semantics) --------------
__device__ __forceinline__ uint32_t rotl32(uint32_t v, int r) {
    return (v << r) | (v >> (32 - r));
}

__device__ __forceinline__ void tf2x32(uint32_t k0, uint32_t k1,
                                       uint32_t x0, uint32_t x1,
                                       uint32_t& o0, uint32_t& o1) {
    uint32_t ks2 = k0 ^ k1 ^ 0x1BD11BDAu;
    x0 += k0; x1 += k1;
#define TF_R(r) { x0 += x1; x1 = rotl32(x1, r); x1 ^= x0; }
    TF_R(13) TF_R(15) TF_R(26) TF_R(6)   x0 += k1;  x1 += ks2 + 1u;
    TF_R(17) TF_R(29) TF_R(16) TF_R(24)  x0 += ks2; x1 += k0 + 2u;
    TF_R(13) TF_R(15) TF_R(26) TF_R(6)   x0 += k0;  x1 += k1 + 3u;
    TF_R(17) TF_R(29) TF_R(16) TF_R(24)  x0 += k1;  x1 += ks2 + 4u;
    TF_R(13) TF_R(15) TF_R(26) TF_R(6)   x0 += ks2; x1 += k0 + 5u;
#undef TF_R
    o0 = x0; o1 = x1;
}

__device__ __forceinline__ bool drop_keep(uint32_t ka, uint32_t kb, uint32_t idx) {
    uint32_t a, b;
    tf2x32(ka, kb, 0u, idx, a, b);
    uint32_t bits = a ^ b;
    float u = __uint_as_float((bits >> 9) | 0x3F800000u) - 1.0f;
    return u < 0.8f;
}

// ---------------- shared-memory overlays ----------------------------------
struct SmemFc1  { float As[32][64]; float Bs[32][64]; };                  // 16384 B
struct SmemPnd  { float en[H]; float ed[H]; };                            //  8192 B
struct SmemNorm { float red[256]; };                                      //  1024 B
struct SmemCp   { float As[16][64]; float Bs[16][64]; float base[64]; };  //  8448 B
struct SmemXY   { float Hs[32][33]; float Ys[32][33]; float ws[32]; };    //  8576 B
struct SmemXC   { float Hs[32][33]; float Cs[32][17]; float Ws[32][9]; }; //  7552 B

#define SMEM_BYTES 16384

// ---------------- part: 1 + l2norm of one row ------------------------------
__device__ void part_norm(char* smem, int r,
                          const float* __restrict__ ye,
                          const float* __restrict__ ce) {
    SmemNorm& s = *reinterpret_cast<SmemNorm*>(smem);
    const float* src;
    float* dst;
    if (r < C) { src = ye + (size_t)r * H;        dst = g_y1 + (size_t)r * H; }
    else       { src = ce + (size_t)(r - C) * H;  dst = g_c1 + (size_t)(r - C) * H; }
    int t = threadIdx.x;
    float4 v = *reinterpret_cast<const float4*>(&src[t * 4]);
    s.red[t] = v.x * v.x + v.y * v.y + v.z * v.z + v.w * v.w;
    __syncthreads();
    for (int o = 128; o; o >>= 1) {
        if (t < o) s.red[t] += s.red[t + o];
        __syncthreads();
    }
    float n = fmaxf(sqrtf(s.red[0]), 1e-12f);
    dst[t * 4 + 0] = 1.0f + v.x / n;
    dst[t * 4 + 1] = 1.0f + v.y / n;
    dst[t * 4 + 2] = 1.0f + v.z / n;
    dst[t * 4 + 3] = 1.0f + v.w / n;
}

// ---------------- part: fc1 GEMM + bias + dropout --------------------------
__device__ void part_fc1(char* smem, int which, int n0, int m0,
                         const float* __restrict__ x,
                         const float* __restrict__ W,
                         const float* __restrict__ B,
                         float* __restrict__ out) {
    SmemFc1& s = *reinterpret_cast<SmemFc1*>(smem);
    const int tid = threadIdx.x;
    const int tx = tid % 16, ty = tid / 16;
    const int lr = tid / 8;          // 0..31
    const int lc = (tid % 8) * 4;    // 0..28
    float acc[4][4] = {};
    for (int k0 = 0; k0 < D; k0 += 32) {
#pragma unroll
        for (int rr = 0; rr < 2; rr++) {
            int r = lr + rr * 32;
            float4 va = *reinterpret_cast<const float4*>(&x[(size_t)(m0 + r) * D + k0 + lc]);
            s.As[lc + 0][r] = va.x; s.As[lc + 1][r] = va.y;
            s.As[lc + 2][r] = va.z; s.As[lc + 3][r] = va.w;
            float4 vb = *reinterpret_cast<const float4*>(&W[(size_t)(n0 + r) * D + k0 + lc]);
            s.Bs[lc + 0][r] = vb.x; s.Bs[lc + 1][r] = vb.y;
            s.Bs[lc + 2][r] = vb.z; s.Bs[lc + 3][r] = vb.w;
        }
        __syncthreads();
#pragma unroll
        for (int kk = 0; kk < 32; kk++) {
            float4 a = *reinterpret_cast<const float4*>(&s.As[kk][ty * 4]);
            float4 b = *reinterpret_cast<const float4*>(&s.Bs[kk][tx * 4]);
            float av[4] = {a.x, a.y, a.z, a.w};
            float bv[4] = {b.x, b.y, b.z, b.w};
#pragma unroll
            for (int i = 0; i < 4; i++)
#pragma unroll
                for (int j = 0; j < 4; j++)
                    acc[i][j] = fmaf(av[i], bv[j], acc[i][j]);
        }
        __syncthreads();
    }
    uint32_t ka, kb;
    tf2x32(0u, 42u, 0u, (uint32_t)which, ka, kb);
#pragma unroll
    for (int i = 0; i < 4; i++) {
        int b = m0 + ty * 4 + i;
#pragma unroll
        for (int j = 0; j < 4; j++) {
            int col = n0 + tx * 4 + j;
            float h = acc[i][j] + B[col];
            uint32_t idx = (uint32_t)(b * H + col);
            out[(size_t)b * H + col] = drop_keep(ka, kb, idx) ? h / 0.8f : 0.0f;
        }
    }
}

// ---------------- part: stream concept_proj_w once --------------------------
__device__ void part_pnd(char* smem, int n, int jg,
                         const float* __restrict__ ce,
                         const float* __restrict__ W) {
    SmemPnd& s = *reinterpret_cast<SmemPnd*>(smem);
    const int tid = threadIdx.x;
    {
        int i = tid * 4;
        float4 ep = *reinterpret_cast<const float4*>(&ce[(size_t)n * H + i]);
        float4 en = *reinterpret_cast<const float4*>(&ce[(size_t)(NC + n) * H + i]);
        *reinterpret_cast<float4*>(&s.en[i]) = en;
        float4 ed = make_float4(ep.x - en.x, ep.y - en.y, ep.z - en.z, ep.w - en.w);
        *reinterpret_cast<float4*>(&s.ed[i]) = ed;
    }
    __syncthreads();
    const int w = tid / 32, lane = tid % 32;
    const int j = jg * 8 + w;
    const float* Wr = W + (size_t)j * (NC * H) + (size_t)n * H;
    float pn = 0.f, pd = 0.f;
#pragma unroll
    for (int c = 0; c < 8; c++) {
        int hh = c * 128 + lane * 4;
        float4 wv = *reinterpret_cast<const float4*>(&Wr[hh]);
        float4 en = *reinterpret_cast<const float4*>(&s.en[hh]);
        float4 ed = *reinterpret_cast<const float4*>(&s.ed[hh]);
        pn += wv.x * en.x + wv.y * en.y + wv.z * en.z + wv.w * en.w;
        pd += wv.x * ed.x + wv.y * ed.y + wv.z * ed.z + wv.w * ed.w;
    }
#pragma unroll
    for (int off = 16; off; off >>= 1) {
        pn += __shfl_down_sync(0xFFFFFFFFu, pn, off);
        pd += __shfl_down_sync(0xFFFFFFFFu, pd, off);
    }
    if (lane == 0) {
        g_pn[n * H + j] = pn;
        g_pd[n * H + j] = pd;
    }
}

// ---------------- part: c_proj = (bias + sum_n pn) + gt @ pd ----------------
__device__ void part_cproj(char* smem, int j0, int m0,
                           const int* __restrict__ cgt,
                           const float* __restrict__ bias) {
    SmemCp& s = *reinterpret_cast<SmemCp*>(smem);
    const int tid = threadIdx.x;
    // base[j] for this 64-column tile (4 chunks of 28 n each, smem-atomic reduce)
    {
        int col = j0 + (tid & 63);
        if (tid < 64) s.base[tid] = bias[col];
        __syncthreads();
        int nb = (tid >> 6) * 28;
        float part = 0.f;
#pragma unroll 4
        for (int n = nb; n < nb + 28; n++) part += g_pn[n * H + col];
        atomicAdd(&s.base[tid & 63], part);
    }
    const int tx = tid % 16, ty = tid / 16;
    float acc[4][4] = {};
    for (int k0 = 0; k0 < NC; k0 += 16) {
        __syncthreads();
        {
            int r = tid / 4;
            int c = (tid % 4) * 4;
            int b = m0 + r;
#pragma unroll
            for (int q = 0; q < 4; q++)
                s.As[c + q][r] = (cgt[(size_t)b * NC + k0 + c + q] == 1) ? 1.0f : 0.0f;
        }
        {
            int kk = tid / 16;
            int j4 = (tid % 16) * 4;
            float4 v = *reinterpret_cast<const float4*>(&g_pd[(size_t)(k0 + kk) * H + j0 + j4]);
            *reinterpret_cast<float4*>(&s.Bs[kk][j4]) = v;
        }
        __syncthreads();
#pragma unroll
        for (int kk = 0; kk < 16; kk++) {
            float4 a = *reinterpret_cast<const float4*>(&s.As[kk][ty * 4]);
            float4 b = *reinterpret_cast<const float4*>(&s.Bs[kk][tx * 4]);
            float av[4] = {a.x, a.y, a.z, a.w};
            float bv[4] = {b.x, b.y, b.z, b.w};
#pragma unroll
            for (int i = 0; i < 4; i++)
#pragma unroll
                for (int j = 0; j < 4; j++)
                    acc[i][j] = fmaf(av[i], bv[j], acc[i][j]);
        }
    }
#pragma unroll
    for (int i = 0; i < 4; i++) {
        int b = m0 + ty * 4 + i;
#pragma unroll
        for (int j = 0; j < 4; j++) {
            int col = j0 + tx * 4 + j;
            g_cproj[(size_t)b * H + col] = acc[i][j] + s.base[tx * 4 + j];
        }
    }
}

// ---------------- part: xy / cy energy --------------------------------------
__device__ void part_xycy(char* smem, int c0, int b0,
                          const float* __restrict__ A,
                          const float* __restrict__ clsw,
                          float bias,
                          float* __restrict__ out) {
    SmemXY& s = *reinterpret_cast<SmemXY*>(smem);
    const int tid = threadIdx.x;
    const int tx = tid % 16, ty = tid / 16;
    const int lr = tid / 8;
    const int lc = (tid % 8) * 4;
    float acc[2][2] = {};
    for (int k0 = 0; k0 < H; k0 += 32) {
        {
            float4 v = *reinterpret_cast<const float4*>(&A[(size_t)(b0 + lr) * H + k0 + lc]);
            s.Hs[lc + 0][lr] = v.x; s.Hs[lc + 1][lr] = v.y;
            s.Hs[lc + 2][lr] = v.z; s.Hs[lc + 3][lr] = v.w;
            int cr = c0 + lr; if (cr > C - 1) cr = C - 1;
            float4 u = *reinterpret_cast<const float4*>(&g_y1[(size_t)cr * H + k0 + lc]);
            s.Ys[lc + 0][lr] = u.x; s.Ys[lc + 1][lr] = u.y;
            s.Ys[lc + 2][lr] = u.z; s.Ys[lc + 3][lr] = u.w;
            if (tid < 32) s.ws[tid] = clsw[k0 + tid];
        }
        __syncthreads();
#pragma unroll
        for (int kk = 0; kk < 32; kk++) {
            float a0 = s.Hs[kk][ty * 2 + 0];
            float a1 = s.Hs[kk][ty * 2 + 1];
            float y0 = s.Ys[kk][tx * 2 + 0];
            float y1v = s.Ys[kk][tx * 2 + 1];
            float w = s.ws[kk];
            acc[0][0] = fmaf(fmaxf(a0 * y0, 0.f), w, acc[0][0]);
            acc[0][1] = fmaf(fmaxf(a0 * y1v, 0.f), w, acc[0][1]);
            acc[1][0] = fmaf(fmaxf(a1 * y0, 0.f), w, acc[1][0]);
            acc[1][1] = fmaf(fmaxf(a1 * y1v, 0.f), w, acc[1][1]);
        }
        __syncthreads();
    }
#pragma unroll
    for (int i = 0; i < 2; i++) {
        int b = b0 + ty * 2 + i;
#pragma unroll
        for (int j = 0; j < 2; j++) {
            int c = c0 + tx * 2 + j;
            if (c < C) out[(size_t)b * C + c] = acc[i][j] + bias;
        }
    }
}

// ---------------- part: xc energy -------------------------------------------
__device__ void part_xc(char* smem, int n0, int b0,
                        const float* __restrict__ xcw,
                        const float* __restrict__ xcb,
                        float* __restrict__ out) {
    SmemXC& s = *reinterpret_cast<SmemXC*>(smem);
    const int tid = threadIdx.x;
    const int tx = tid % 8;   // n_local
    const int ty = tid / 8;   // b_local 0..31
    const int lr = tid / 8;
    const int lc = (tid % 8) * 4;
    float acc0 = 0.f, acc1 = 0.f;
    for (int k0 = 0; k0 < H; k0 += 32) {
        {
            float4 v = *reinterpret_cast<const float4*>(&g_hxc[(size_t)(b0 + lr) * H + k0 + lc]);
            s.Hs[lc + 0][lr] = v.x; s.Hs[lc + 1][lr] = v.y;
            s.Hs[lc + 2][lr] = v.z; s.Hs[lc + 3][lr] = v.w;
        }
        {
            int loc = tid / 16;
            int kk = (tid % 16) * 2;
            int nl = loc >> 1, sx = loc & 1;
            int row = sx * NC + (n0 + nl);
            float2 v = *reinterpret_cast<const float2*>(&g_c1[(size_t)row * H + k0 + kk]);
            s.Cs[kk + 0][nl * 2 + sx] = v.x;
            s.Cs[kk + 1][nl * 2 + sx] = v.y;
        }
        {
            int nl = tid / 32;
            int kk = tid % 32;
            s.Ws[kk][nl] = xcw[(size_t)(n0 + nl) * H + k0 + kk];
        }
        __syncthreads();
#pragma unroll
        for (int kk = 0; kk < 32; kk++) {
            float h = s.Hs[kk][ty];
            float w = s.Ws[kk][tx];
            float cp = s.Cs[kk][tx * 2 + 0];
            float cn = s.Cs[kk][tx * 2 + 1];
            acc0 = fmaf(fmaxf(h * cp, 0.f), w, acc0);
            acc1 = fmaf(fmaxf(h * cn, 0.f), w, acc1);
        }
        __syncthreads();
    }
    int b = b0 + ty, n = n0 + tx;
    float bb = xcb[n];
    size_t base = (size_t)(2 * BS * C) + (size_t)b * (NC * 2) + n * 2;
    out[base + 0] = acc0 + bb;
    out[base + 1] = acc1 + bb;
}

// ================= launch 1: fc1 + norm + pnd (overlapped) ==================
#define L1_FC1   128
#define L1_NORM  (C + 2 * NC)                 // 424
#define L1_PND   (NC * (H / 8))               // 14336
#define L1_GRID  (L1_FC1 + L1_NORM + L1_PND)  // 14888

__global__ __launch_bounds__(256) void k_main(const float* __restrict__ x,
                                              const float* __restrict__ ye,
                                              const float* __restrict__ ce,
                                              const float* __restrict__ w0,
                                              const float* __restrict__ b0,
                                              const float* __restrict__ w1,
                                              const float* __restrict__ b1,
                                              const float* __restrict__ cpw) {
    __shared__ __align__(16) char smem[SMEM_BYTES];
    int bid = blockIdx.x;
    if (bid < L1_FC1) {
        int which = bid >> 6;
        int rem = bid & 63;
        part_fc1(smem, which, (rem % 16) * 64, (rem / 16) * 64, x,
                 which ? w1 : w0, which ? b1 : b0, which ? g_hxc : g_hxy);
    } else if (bid < L1_FC1 + L1_NORM) {
        part_norm(smem, bid - L1_FC1, ye, ce);
    } else {
        int p = bid - (L1_FC1 + L1_NORM);
        part_pnd(smem, p % NC, p / NC, ce, cpw);
    }
}

// ================= launch 2: cproj + xy-energy + xc-energy ==================
#define L2_CP   (16 * 4)              // 64
#define L2_XY   (7 * 8)               // 56
#define L2_XC   (14 * 8)              // 112
#define L2_GRID (L2_CP + L2_XY + L2_XC)

__global__ __launch_bounds__(256) void k_mid(const int* __restrict__ cgt,
                                             const float* __restrict__ cpb,
                                             const float* __restrict__ clsxy_w,
                                             const float* __restrict__ clsxy_b,
                                             const float* __restrict__ xcw,
                                             const float* __restrict__ xcb,
                                             float* __restrict__ out) {
    __shared__ __align__(16) char smem[SMEM_BYTES];
    int bid = blockIdx.x;
    if (bid < L2_CP) {
        part_cproj(smem, (bid % 16) * 64, (bid / 16) * 64, cgt, cpb);
    } else if (bid < L2_CP + L2_XY) {
        int p = bid - L2_CP;
        part_xycy(smem, (p % 7) * 32, (p / 7) * 32, g_hxy, clsxy_w, clsxy_b[0], out);
    } else {
        int p = bid - (L2_CP + L2_XY);
        part_xc(smem, (p % 14) * 8, (p / 14) * 32, xcw, xcb, out);
    }
}

// ================= launch 3: cy-energy ======================================
__global__ __launch_bounds__(256) void k_cy(const float* __restrict__ clscy_w,
                                            const float* __restrict__ clscy_b,
                                            float* __restrict__ out) {
    __shared__ __align__(16) char smem[SMEM_BYTES];
    int bid = blockIdx.x;
    part_xycy(smem, (bid % 7) * 32, (bid / 7) * 32, g_cproj, clscy_w, clscy_b[0],
              out + (size_t)BS * C);
}

// ---------------- launch ----------------------------------------------------
extern "C" void kernel_launch(void* const* d_in, const int* in_sizes, int n_in,
                              void* d_out, int out_size) {
    (void)in_sizes; (void)n_in; (void)out_size;
    const float* x       = (const float*)d_in[0];
    const int*   c_gt    = (const int*)d_in[1];
    const float* y_emb   = (const float*)d_in[2];
    const float* c_emb   = (const float*)d_in[3];
    const float* xy_w    = (const float*)d_in[4];
    const float* xy_b    = (const float*)d_in[5];
    const float* xc_w1   = (const float*)d_in[6];
    const float* xc_b1   = (const float*)d_in[7];
    const float* clsxy_w = (const float*)d_in[8];
    const float* clsxy_b = (const float*)d_in[9];
    const float* clscy_w = (const float*)d_in[10];
    const float* clscy_b = (const float*)d_in[11];
    const float* xcw     = (const float*)d_in[12];
    const float* xcb     = (const float*)d_in[13];
    const float* cpw     = (const float*)d_in[14];
    const float* cpb     = (const float*)d_in[15];
    float* out = (float*)d_out;

    k_main<<<L1_GRID, 256>>>(x, y_emb, c_emb, xy_w, xy_b, xc_w1, xc_b1, cpw);
    k_mid<<<L2_GRID, 256>>>(c_gt, cpb, clsxy_w, clsxy_b, xcw, xcb, out);
    k_cy<<<7 * 8, 256>>>(clscy_w, clscy_b, out);
}